// round 3
// baseline (speedup 1.0000x reference)
#include <cuda_runtime.h>
#include <cuda_bf16.h>
#include <math.h>

#define NN    50000
#define DH    256
#define DOUT  128
#define EMAX  800000

// ---------------- scratch (device globals; referenced by symbol only) --------
__device__ float g_h   [(size_t)NN * DH];   // GEMM output scratch
__device__ float g_a   [(size_t)NN * DH];   // aggregation output / next input
__device__ float g_deg [NN];
__device__ float g_dinv[NN];
__device__ int   g_src [EMAX];
__device__ int   g_dst [EMAX];
__device__ float g_norm[EMAX];
__device__ int   g_is64;                    // 1 if edge_index is int64

// ---------------- dtype probe ------------------------------------------------
// int64 values < 50000 => every odd int32 word (high half) is 0.
// int32 edge list      => odd words are src values, almost surely nonzero.
__global__ void k_detect(const int* __restrict__ ei32) {
    __shared__ int any;
    if (threadIdx.x == 0) any = 0;
    __syncthreads();
    for (int k = threadIdx.x; k < 1024; k += blockDim.x)
        if (ei32[2 * k + 1] != 0) atomicOr(&any, 1);
    __syncthreads();
    if (threadIdx.x == 0) g_is64 = any ? 0 : 1;
}

// ---------------- degree / norm precompute ----------------------------------
__device__ __forceinline__ int ld_idx(const void* ei, size_t pos) {
    int v;
    if (g_is64) v = (int)((const long long*)ei)[pos];
    else        v = ((const int*)ei)[pos];
    return min(max(v, 0), NN - 1);
}

__global__ void k_deg_init(int n) {
    int i = blockIdx.x * blockDim.x + threadIdx.x;
    if (i < n) g_deg[i] = 1.0f;   // self-loop contributes 1
}

__global__ void k_deg_acc(const void* __restrict__ ei, int E) {
    int e = blockIdx.x * blockDim.x + threadIdx.x;
    if (e < E) {
        int d = ld_idx(ei, (size_t)E + e);   // dst row
        atomicAdd(&g_deg[d], 1.0f);
    }
}

__global__ void k_dinv(int n) {
    int i = blockIdx.x * blockDim.x + threadIdx.x;
    if (i < n) g_dinv[i] = rsqrtf(g_deg[i]);   // deg >= 1 (self-loops)
}

__global__ void k_prep(const void* __restrict__ ei, int E) {
    int e = blockIdx.x * blockDim.x + threadIdx.x;
    if (e < E) {
        int s = ld_idx(ei, (size_t)e);
        int d = ld_idx(ei, (size_t)E + e);
        g_src[e]  = s;
        g_dst[e]  = d;
        g_norm[e] = g_dinv[s] * g_dinv[d];
    }
}

// ---------------- SGEMM: g_h[N,M] = A[N,K] @ W[K,M], optional relu on A ------
// A = xext (useExt) or g_a. 64x64 tile, 256 threads, 4x4 micro-tile, K-step 32.
__global__ __launch_bounds__(256) void k_gemm_g(
    const float* __restrict__ xext, const float* __restrict__ W,
    int N, int K, int M, int relu, int useExt)
{
    const float* A = useExt ? xext : g_a;
    float*       C = g_h;

    __shared__ float As[64][33];
    __shared__ float Ws[32][64];

    const int tid = threadIdx.x;
    const int tx  = tid & 15;
    const int ty  = tid >> 4;
    const int row0 = blockIdx.x * 64;
    const int col0 = blockIdx.y * 64;

    float acc[4][4] = {};

    for (int k0 = 0; k0 < K; k0 += 32) {
        #pragma unroll
        for (int l = 0; l < 2; l++) {
            int idx = tid + l * 256;          // 0..511
            int r   = idx >> 3;               // 8 float4 per row
            int c4  = idx & 7;
            float4 v = make_float4(0.f, 0.f, 0.f, 0.f);
            int row = row0 + r;
            if (row < N)
                v = *(const float4*)&A[(size_t)row * K + k0 + c4 * 4];
            if (relu) {
                v.x = fmaxf(v.x, 0.f); v.y = fmaxf(v.y, 0.f);
                v.z = fmaxf(v.z, 0.f); v.w = fmaxf(v.w, 0.f);
            }
            As[r][c4 * 4 + 0] = v.x;
            As[r][c4 * 4 + 1] = v.y;
            As[r][c4 * 4 + 2] = v.z;
            As[r][c4 * 4 + 3] = v.w;
        }
        #pragma unroll
        for (int l = 0; l < 2; l++) {
            int idx = tid + l * 256;
            int r   = idx >> 4;               // 16 float4 per row
            int c4  = idx & 15;
            float4 v = *(const float4*)&W[(size_t)(k0 + r) * M + col0 + c4 * 4];
            *(float4*)&Ws[r][c4 * 4] = v;
        }
        __syncthreads();

        #pragma unroll
        for (int k = 0; k < 32; k++) {
            float a[4];
            #pragma unroll
            for (int i = 0; i < 4; i++) a[i] = As[ty * 4 + i][k];
            float4 bb = *(float4*)&Ws[k][tx * 4];
            float b[4] = { bb.x, bb.y, bb.z, bb.w };
            #pragma unroll
            for (int i = 0; i < 4; i++)
                #pragma unroll
                for (int j = 0; j < 4; j++)
                    acc[i][j] = fmaf(a[i], b[j], acc[i][j]);
        }
        __syncthreads();
    }

    #pragma unroll
    for (int i = 0; i < 4; i++) {
        int row = row0 + ty * 4 + i;
        if (row < N) {
            float4 v = make_float4(acc[i][0], acc[i][1], acc[i][2], acc[i][3]);
            *(float4*)&C[(size_t)row * M + col0 + tx * 4] = v;
        }
    }
}

// ---------------- aggregation: out = b + self-loop + edge scatter ------------
__global__ void k_agg_init(const float* __restrict__ b, float* __restrict__ oext,
                           int N, int M, int useExt)
{
    float* out = useExt ? oext : g_a;
    int idx = blockIdx.x * blockDim.x + threadIdx.x;
    int total = N * (M >> 2);
    if (idx < total) {
        int row = idx / (M >> 2);
        int c   = idx % (M >> 2);
        float di = g_dinv[row];
        float s  = di * di;                 // self-loop norm
        float4 hv = *(const float4*)&g_h[(size_t)row * M + c * 4];
        float4 bv = *(const float4*)&b[c * 4];
        float4 o;
        o.x = fmaf(hv.x, s, bv.x);
        o.y = fmaf(hv.y, s, bv.y);
        o.z = fmaf(hv.z, s, bv.z);
        o.w = fmaf(hv.w, s, bv.w);
        *(float4*)&out[(size_t)row * M + c * 4] = o;
    }
}

__global__ void k_scatter(float* __restrict__ oext, int E, int M, int useExt)
{
    float* out = useExt ? oext : g_a;
    int c4  = M >> 2;                        // float4s per row (64 or 32)
    int epb = 256 / c4;                      // edges per block (4 or 8)
    int tid = threadIdx.x;
    int e   = blockIdx.x * epb + tid / c4;
    int c   = tid % c4;
    if (e < E) {
        int   s = g_src[e];
        int   d = g_dst[e];
        float w = g_norm[e];
        float4 v = *(const float4*)&g_h[(size_t)s * M + c * 4];
        float* o = &out[(size_t)d * M + c * 4];
        atomicAdd(o + 0, v.x * w);
        atomicAdd(o + 1, v.y * w);
        atomicAdd(o + 2, v.z * w);
        atomicAdd(o + 3, v.w * w);
    }
}

// ---------------- launch -----------------------------------------------------
extern "C" void kernel_launch(void* const* d_in, const int* in_sizes, int n_in,
                              void* d_out, int out_size)
{
    const float* x  = (const float*)d_in[0];
    const void*  ei = d_in[1];
    const float* W1 = (const float*)d_in[2];
    const float* b1 = (const float*)d_in[3];
    const float* W2 = (const float*)d_in[4];
    const float* b2 = (const float*)d_in[5];
    const float* W3 = (const float*)d_in[6];
    const float* b3 = (const float*)d_in[7];
    float* out = (float*)d_out;

    const int N = NN;
    const int E = in_sizes[1] / 2;

    // ---- dtype probe + degree/norm precompute (reused by all 3 layers)
    k_detect  <<<1, 256>>>((const int*)ei);
    k_deg_init<<<(N + 255) / 256, 256>>>(N);
    k_deg_acc <<<(E + 255) / 256, 256>>>(ei, E);
    k_dinv    <<<(N + 255) / 256, 256>>>(N);
    k_prep    <<<(E + 255) / 256, 256>>>(ei, E);

    dim3 gemm_grid_h((N + 63) / 64, DH / 64);    // 782 x 4
    dim3 gemm_grid_o((N + 63) / 64, DOUT / 64);  // 782 x 2

    int init_thr_h = N * (DH / 4);
    int init_thr_o = N * (DOUT / 4);
    int scat_blk_h = (E + 3) / 4;                // 4 edges/block @ M=256
    int scat_blk_o = (E + 7) / 8;                // 8 edges/block @ M=128

    // ---- layer 1: g_h = x @ W1 ; g_a = agg(g_h) + b1
    k_gemm_g  <<<gemm_grid_h, 256>>>(x, W1, N, DH, DH, 0, 1);
    k_agg_init<<<(init_thr_h + 255) / 256, 256>>>(b1, out, N, DH, 0);
    k_scatter <<<scat_blk_h, 256>>>(out, E, DH, 0);

    // ---- layer 2: g_h = relu(g_a) @ W2 ; g_a = agg(g_h) + b2
    k_gemm_g  <<<gemm_grid_h, 256>>>(x, W2, N, DH, DH, 1, 0);
    k_agg_init<<<(init_thr_h + 255) / 256, 256>>>(b2, out, N, DH, 0);
    k_scatter <<<scat_blk_h, 256>>>(out, E, DH, 0);

    // ---- layer 3: g_h = relu(g_a) @ W3 ; out = agg(g_h) + b3
    k_gemm_g  <<<gemm_grid_o, 256>>>(x, W3, N, DH, DOUT, 1, 0);
    k_agg_init<<<(init_thr_o + 255) / 256, 256>>>(b3, out, N, DOUT, 1);
    k_scatter <<<scat_blk_o, 256>>>(out, E, DOUT, 1);
}

// round 4
// speedup vs baseline: 1.4984x; 1.4984x over previous
#include <cuda_runtime.h>
#include <cuda_bf16.h>
#include <math.h>

#define NN    50000
#define DH    256
#define DOUT  128
#define EMAX  800000

// ---------------- scratch (device globals; referenced by symbol only) --------
__device__ float g_h   [(size_t)NN * DH];   // GEMM output scratch
__device__ float g_a   [(size_t)NN * DH];   // aggregation output / next input
__device__ float g_dinv[NN];
__device__ int   g_cnt [NN];
__device__ int   g_rowptr[NN + 1];
__device__ int   g_cursor[NN];
__device__ int   g_src [EMAX];
__device__ int   g_dst [EMAX];
__device__ float g_norm[EMAX];
__device__ int   g_csr_src[EMAX];
__device__ float g_csr_w  [EMAX];
__device__ int   g_is64;                    // 1 if edge_index is int64

// ---------------- dtype probe ------------------------------------------------
// int64 values < 50000 => every odd int32 word (high half) is 0.
__global__ void k_detect(const int* __restrict__ ei32) {
    __shared__ int any;
    if (threadIdx.x == 0) any = 0;
    __syncthreads();
    for (int k = threadIdx.x; k < 1024; k += blockDim.x)
        if (ei32[2 * k + 1] != 0) atomicOr(&any, 1);
    __syncthreads();
    if (threadIdx.x == 0) g_is64 = any ? 0 : 1;
}

__device__ __forceinline__ int ld_idx(const void* ei, size_t pos) {
    int v;
    if (g_is64) v = (int)((const long long*)ei)[pos];
    else        v = ((const int*)ei)[pos];
    return min(max(v, 0), NN - 1);
}

// ---------------- degree count ----------------------------------------------
__global__ void k_cnt_init(int n) {
    int i = blockIdx.x * blockDim.x + threadIdx.x;
    if (i < n) g_cnt[i] = 0;
}

__global__ void k_cnt_acc(const void* __restrict__ ei, int E) {
    int e = blockIdx.x * blockDim.x + threadIdx.x;
    if (e < E) atomicAdd(&g_cnt[ld_idx(ei, (size_t)E + e)], 1);
}

__global__ void k_dinv(int n) {
    int i = blockIdx.x * blockDim.x + threadIdx.x;
    if (i < n) g_dinv[i] = rsqrtf(1.0f + (float)g_cnt[i]);  // +1 self-loop
}

__global__ void k_prep(const void* __restrict__ ei, int E) {
    int e = blockIdx.x * blockDim.x + threadIdx.x;
    if (e < E) {
        int s = ld_idx(ei, (size_t)e);
        int d = ld_idx(ei, (size_t)E + e);
        g_src[e]  = s;
        g_dst[e]  = d;
        g_norm[e] = g_dinv[s] * g_dinv[d];
    }
}

// ---------------- exclusive scan over g_cnt (single block) -------------------
__global__ void k_scan() {
    const int T = 1024;
    __shared__ int part[T];
    int tid = threadIdx.x;
    int chunk = (NN + T - 1) / T;
    int base = tid * chunk;
    int sum = 0;
    for (int i = 0; i < chunk; i++) {
        int j = base + i;
        if (j < NN) sum += g_cnt[j];
    }
    part[tid] = sum;
    __syncthreads();
    for (int off = 1; off < T; off <<= 1) {
        int v = (tid >= off) ? part[tid - off] : 0;
        __syncthreads();
        part[tid] += v;
        __syncthreads();
    }
    int run = (tid > 0) ? part[tid - 1] : 0;
    for (int i = 0; i < chunk; i++) {
        int j = base + i;
        if (j < NN) {
            int c = g_cnt[j];
            g_rowptr[j] = run;
            g_cursor[j] = run;
            run += c;
        }
    }
    if (tid == T - 1) g_rowptr[NN] = run;
}

// ---------------- CSR fill (counting-sort scatter) ---------------------------
__global__ void k_fill(int E) {
    int e = blockIdx.x * blockDim.x + threadIdx.x;
    if (e < E) {
        int d   = g_dst[e];
        int pos = atomicAdd(&g_cursor[d], 1);
        g_csr_src[pos] = g_src[e];
        g_csr_w  [pos] = g_norm[e];
    }
}

// ---------------- SGEMM: g_h[N,M] = A[N,K] @ W[K,M], optional relu on A ------
// 128x128 block tile, 256 threads, 8x8 micro-tile, K-step 16, A transposed.
__global__ __launch_bounds__(256) void k_gemm_g(
    const float* __restrict__ xext, const float* __restrict__ W,
    int N, int K, int M, int relu, int useExt)
{
    const float* A = useExt ? xext : g_a;
    float*       C = g_h;

    __shared__ float As[16][128];   // [k][row]
    __shared__ float Ws[16][128];   // [k][col]

    const int tid = threadIdx.x;
    const int tx  = tid & 15;       // col group: cols tx*8 .. tx*8+7
    const int ty  = tid >> 4;       // row group: rows ty*8 .. ty*8+7
    const int row0 = blockIdx.x * 128;
    const int col0 = blockIdx.y * 128;

    float acc[8][8] = {};

    for (int k0 = 0; k0 < K; k0 += 16) {
        // A tile: 128 rows x 16 k = 512 float4, transposed into As[k][row]
        #pragma unroll
        for (int l = 0; l < 2; l++) {
            int idx = tid + l * 256;
            int r   = idx >> 2;             // 4 float4 per row
            int c4  = idx & 3;
            float4 v = make_float4(0.f, 0.f, 0.f, 0.f);
            int row = row0 + r;
            if (row < N)
                v = *(const float4*)&A[(size_t)row * K + k0 + c4 * 4];
            if (relu) {
                v.x = fmaxf(v.x, 0.f); v.y = fmaxf(v.y, 0.f);
                v.z = fmaxf(v.z, 0.f); v.w = fmaxf(v.w, 0.f);
            }
            As[c4 * 4 + 0][r] = v.x;
            As[c4 * 4 + 1][r] = v.y;
            As[c4 * 4 + 2][r] = v.z;
            As[c4 * 4 + 3][r] = v.w;
        }
        // W tile: 16 rows x 128 cols = 512 float4
        #pragma unroll
        for (int l = 0; l < 2; l++) {
            int idx = tid + l * 256;
            int r   = idx >> 5;             // 32 float4 per row
            int c4  = idx & 31;
            *(float4*)&Ws[r][c4 * 4] =
                *(const float4*)&W[(size_t)(k0 + r) * M + col0 + c4 * 4];
        }
        __syncthreads();

        #pragma unroll
        for (int k = 0; k < 16; k++) {
            float4 a0 = *(float4*)&As[k][ty * 8];
            float4 a1 = *(float4*)&As[k][ty * 8 + 4];
            float4 b0 = *(float4*)&Ws[k][tx * 8];
            float4 b1 = *(float4*)&Ws[k][tx * 8 + 4];
            float a[8] = { a0.x, a0.y, a0.z, a0.w, a1.x, a1.y, a1.z, a1.w };
            float b[8] = { b0.x, b0.y, b0.z, b0.w, b1.x, b1.y, b1.z, b1.w };
            #pragma unroll
            for (int i = 0; i < 8; i++)
                #pragma unroll
                for (int j = 0; j < 8; j++)
                    acc[i][j] = fmaf(a[i], b[j], acc[i][j]);
        }
        __syncthreads();
    }

    #pragma unroll
    for (int i = 0; i < 8; i++) {
        int row = row0 + ty * 8 + i;
        if (row < N) {
            float4 v0 = make_float4(acc[i][0], acc[i][1], acc[i][2], acc[i][3]);
            float4 v1 = make_float4(acc[i][4], acc[i][5], acc[i][6], acc[i][7]);
            *(float4*)&C[(size_t)row * M + col0 + tx * 8]     = v0;
            *(float4*)&C[(size_t)row * M + col0 + tx * 8 + 4] = v1;
        }
    }
}

// ---------------- aggregation (gather, atomic-free) --------------------------
// out[d] = b + dinv[d]^2 * h[d] + sum_e norm_e * h[src_e]
// one block per node, M/4 threads, each owns one float4 column slice.
__global__ void k_agg(const float* __restrict__ b, float* __restrict__ oext,
                      int M, int useExt)
{
    float* out = useExt ? oext : g_a;
    int node = blockIdx.x;
    int c    = threadIdx.x;           // 0 .. M/4-1

    float di = g_dinv[node];
    float s  = di * di;
    float4 hv = *(const float4*)&g_h[(size_t)node * M + c * 4];
    float4 bv = *(const float4*)&b[c * 4];
    float4 acc;
    acc.x = fmaf(hv.x, s, bv.x);
    acc.y = fmaf(hv.y, s, bv.y);
    acc.z = fmaf(hv.z, s, bv.z);
    acc.w = fmaf(hv.w, s, bv.w);

    int e   = g_rowptr[node];
    int end = g_rowptr[node + 1];
    for (; e + 1 < end; e += 2) {
        int   s0 = g_csr_src[e];
        int   s1 = g_csr_src[e + 1];
        float w0 = g_csr_w[e];
        float w1 = g_csr_w[e + 1];
        float4 v0 = *(const float4*)&g_h[(size_t)s0 * M + c * 4];
        float4 v1 = *(const float4*)&g_h[(size_t)s1 * M + c * 4];
        acc.x = fmaf(v0.x, w0, acc.x); acc.y = fmaf(v0.y, w0, acc.y);
        acc.z = fmaf(v0.z, w0, acc.z); acc.w = fmaf(v0.w, w0, acc.w);
        acc.x = fmaf(v1.x, w1, acc.x); acc.y = fmaf(v1.y, w1, acc.y);
        acc.z = fmaf(v1.z, w1, acc.z); acc.w = fmaf(v1.w, w1, acc.w);
    }
    if (e < end) {
        int   s0 = g_csr_src[e];
        float w0 = g_csr_w[e];
        float4 v0 = *(const float4*)&g_h[(size_t)s0 * M + c * 4];
        acc.x = fmaf(v0.x, w0, acc.x); acc.y = fmaf(v0.y, w0, acc.y);
        acc.z = fmaf(v0.z, w0, acc.z); acc.w = fmaf(v0.w, w0, acc.w);
    }
    *(float4*)&out[(size_t)node * M + c * 4] = acc;
}

// ---------------- launch -----------------------------------------------------
extern "C" void kernel_launch(void* const* d_in, const int* in_sizes, int n_in,
                              void* d_out, int out_size)
{
    const float* x  = (const float*)d_in[0];
    const void*  ei = d_in[1];
    const float* W1 = (const float*)d_in[2];
    const float* b1 = (const float*)d_in[3];
    const float* W2 = (const float*)d_in[4];
    const float* b2 = (const float*)d_in[5];
    const float* W3 = (const float*)d_in[6];
    const float* b3 = (const float*)d_in[7];
    float* out = (float*)d_out;

    const int N = NN;
    const int E = in_sizes[1] / 2;

    // ---- one-time prep: dtype probe, degrees, norms, CSR by dst
    k_detect  <<<1, 256>>>((const int*)ei);
    k_cnt_init<<<(N + 255) / 256, 256>>>(N);
    k_cnt_acc <<<(E + 255) / 256, 256>>>(ei, E);
    k_dinv    <<<(N + 255) / 256, 256>>>(N);
    k_prep    <<<(E + 255) / 256, 256>>>(ei, E);
    k_scan    <<<1, 1024>>>();
    k_fill    <<<(E + 255) / 256, 256>>>(E);

    dim3 gemm_grid_h((N + 127) / 128, DH / 128);    // 391 x 2
    dim3 gemm_grid_o((N + 127) / 128, DOUT / 128);  // 391 x 1

    // ---- layer 1: g_h = x @ W1 ; g_a = agg(g_h) + b1
    k_gemm_g<<<gemm_grid_h, 256>>>(x, W1, N, DH, DH, 0, 1);
    k_agg   <<<N, DH / 4>>>(b1, out, DH, 0);

    // ---- layer 2: g_h = relu(g_a) @ W2 ; g_a = agg(g_h) + b2
    k_gemm_g<<<gemm_grid_h, 256>>>(x, W2, N, DH, DH, 1, 0);
    k_agg   <<<N, DH / 4>>>(b2, out, DH, 0);

    // ---- layer 3: g_h = relu(g_a) @ W3 ; out = agg(g_h) + b3
    k_gemm_g<<<gemm_grid_o, 256>>>(x, W3, N, DH, DOUT, 1, 0);
    k_agg   <<<N, DOUT / 4>>>(b3, out, DOUT, 1);
}

// round 6
// speedup vs baseline: 2.9696x; 1.9819x over previous
#include <cuda_runtime.h>
#include <cuda_bf16.h>
#include <math.h>
#include <stdint.h>

#define NN    50000
#define DH    256
#define DOUT  128
#define EMAX  800000

// ---------------- scratch (device globals; referenced by symbol only) --------
__device__ float g_h   [(size_t)NN * DH];        // GEMM output (fp32)
__device__ float g_a   [(size_t)NN * DH];        // agg output / next input
__device__ __nv_bfloat16 g_ah[(size_t)NN * DH];  // A split hi
__device__ __nv_bfloat16 g_al[(size_t)NN * DH];  // A split lo
__device__ __nv_bfloat16 g_wth[2 * 65536 + 32768]; // W^T hi (3 layers, [m][k])
__device__ __nv_bfloat16 g_wtl[2 * 65536 + 32768]; // W^T lo
__device__ float g_dinv[NN];
__device__ int   g_cnt [NN];
__device__ int   g_rowptr[NN + 1];
__device__ int   g_cursor[NN];
__device__ int   g_src [EMAX];
__device__ int   g_dst [EMAX];
__device__ float g_norm[EMAX];
__device__ int   g_csr_src[EMAX];
__device__ float g_csr_w  [EMAX];
__device__ int   g_is64;

__device__ __forceinline__ uint32_t smem_u32(const void* p) {
    uint32_t a;
    asm("{ .reg .u64 t; cvta.to.shared.u64 t, %1; cvt.u32.u64 %0, t; }"
        : "=r"(a) : "l"(p));
    return a;
}

// ---------------- dtype probe ------------------------------------------------
__global__ void k_detect(const int* __restrict__ ei32) {
    __shared__ int any;
    if (threadIdx.x == 0) any = 0;
    __syncthreads();
    for (int k = threadIdx.x; k < 1024; k += blockDim.x)
        if (ei32[2 * k + 1] != 0) atomicOr(&any, 1);
    __syncthreads();
    if (threadIdx.x == 0) g_is64 = any ? 0 : 1;
}

__device__ __forceinline__ int ld_idx(const void* ei, size_t pos) {
    int v;
    if (g_is64) v = (int)((const long long*)ei)[pos];
    else        v = ((const int*)ei)[pos];
    return min(max(v, 0), NN - 1);
}

// ---------------- degree / CSR prep ------------------------------------------
__global__ void k_cnt_init(int n) {
    int i = blockIdx.x * blockDim.x + threadIdx.x;
    if (i < n) g_cnt[i] = 0;
}
__global__ void k_cnt_acc(const void* __restrict__ ei, int E) {
    int e = blockIdx.x * blockDim.x + threadIdx.x;
    if (e < E) atomicAdd(&g_cnt[ld_idx(ei, (size_t)E + e)], 1);
}
__global__ void k_dinv(int n) {
    int i = blockIdx.x * blockDim.x + threadIdx.x;
    if (i < n) g_dinv[i] = rsqrtf(1.0f + (float)g_cnt[i]);
}
__global__ void k_prep(const void* __restrict__ ei, int E) {
    int e = blockIdx.x * blockDim.x + threadIdx.x;
    if (e < E) {
        int s = ld_idx(ei, (size_t)e);
        int d = ld_idx(ei, (size_t)E + e);
        g_src[e]  = s;
        g_dst[e]  = d;
        g_norm[e] = g_dinv[s] * g_dinv[d];
    }
}
__global__ void k_scan() {
    const int T = 1024;
    __shared__ int part[T];
    int tid = threadIdx.x;
    int chunk = (NN + T - 1) / T;
    int base = tid * chunk;
    int sum = 0;
    for (int i = 0; i < chunk; i++) {
        int j = base + i;
        if (j < NN) sum += g_cnt[j];
    }
    part[tid] = sum;
    __syncthreads();
    for (int off = 1; off < T; off <<= 1) {
        int v = (tid >= off) ? part[tid - off] : 0;
        __syncthreads();
        part[tid] += v;
        __syncthreads();
    }
    int run = (tid > 0) ? part[tid - 1] : 0;
    for (int i = 0; i < chunk; i++) {
        int j = base + i;
        if (j < NN) {
            int c = g_cnt[j];
            g_rowptr[j] = run;
            g_cursor[j] = run;
            run += c;
        }
    }
    if (tid == T - 1) g_rowptr[NN] = run;
}
__global__ void k_fill(int E) {
    int e = blockIdx.x * blockDim.x + threadIdx.x;
    if (e < E) {
        int d   = g_dst[e];
        int pos = atomicAdd(&g_cursor[d], 1);
        g_csr_src[pos] = g_src[e];
        g_csr_w  [pos] = g_norm[e];
    }
}

// ---------------- hi/lo split conversions -------------------------------------
__device__ __forceinline__ void split1(float v, unsigned short& hb, unsigned short& lb) {
    __nv_bfloat16 h = __float2bfloat16(v);
    float hf = __bfloat162float(h);
    __nv_bfloat16 l = __float2bfloat16(v - hf);
    hb = reinterpret_cast<unsigned short&>(h);
    lb = reinterpret_cast<unsigned short&>(l);
}

__global__ void k_split(const float* __restrict__ xext, int n4, int relu, int useExt) {
    const float* src = useExt ? xext : g_a;
    int i = blockIdx.x * blockDim.x + threadIdx.x;
    if (i < n4) {
        float4 v = ((const float4*)src)[i];
        if (relu) {
            v.x = fmaxf(v.x, 0.f); v.y = fmaxf(v.y, 0.f);
            v.z = fmaxf(v.z, 0.f); v.w = fmaxf(v.w, 0.f);
        }
        ushort4 hv, lv;
        split1(v.x, hv.x, lv.x);
        split1(v.y, hv.y, lv.y);
        split1(v.z, hv.z, lv.z);
        split1(v.w, hv.w, lv.w);
        ((ushort4*)g_ah)[i] = hv;
        ((ushort4*)g_al)[i] = lv;
    }
}

// weights: W[K,M] fp32 -> Wt[m][k] bf16 hi/lo at offset off
__global__ void k_wprep(const float* __restrict__ W, int K, int M, int off) {
    int i = blockIdx.x * blockDim.x + threadIdx.x;
    if (i < K * M) {
        int k = i / M, m = i % M;
        unsigned short hb, lb;
        split1(W[i], hb, lb);
        g_wth[off + (size_t)m * K + k] = reinterpret_cast<__nv_bfloat16&>(hb);
        g_wtl[off + (size_t)m * K + k] = reinterpret_cast<__nv_bfloat16&>(lb);
    }
}

// ---------------- mma.sync bf16 split GEMM ------------------------------------
// g_h[N,M] = (Ah+Al)[N,256] @ (Wh+Wl)^T.  128x128 CTA tile, 8 warps (2x4),
// warp tile 64x32, K-chunk 32, smem row stride 40 bf16 (conflict-free ldmatrix).
#define SSTR 40

__device__ __forceinline__ void ldsm_x4(uint32_t& r0, uint32_t& r1,
                                        uint32_t& r2, uint32_t& r3, uint32_t a) {
    asm volatile("ldmatrix.sync.aligned.m8n8.x4.shared.b16 {%0,%1,%2,%3}, [%4];"
                 : "=r"(r0), "=r"(r1), "=r"(r2), "=r"(r3) : "r"(a));
}
__device__ __forceinline__ void ldsm_x2(uint32_t& r0, uint32_t& r1, uint32_t a) {
    asm volatile("ldmatrix.sync.aligned.m8n8.x2.shared.b16 {%0,%1}, [%2];"
                 : "=r"(r0), "=r"(r1) : "r"(a));
}
__device__ __forceinline__ void mma16816(float* d, const uint32_t* a, const uint32_t* b) {
    asm volatile(
        "mma.sync.aligned.m16n8k16.row.col.f32.bf16.bf16.f32 "
        "{%0,%1,%2,%3}, {%4,%5,%6,%7}, {%8,%9}, {%0,%1,%2,%3};"
        : "+f"(d[0]), "+f"(d[1]), "+f"(d[2]), "+f"(d[3])
        : "r"(a[0]), "r"(a[1]), "r"(a[2]), "r"(a[3]), "r"(b[0]), "r"(b[1]));
}

__global__ __launch_bounds__(256, 1) void k_mgemm(int N, int M, int woff) {
    __shared__ __align__(16) unsigned short sAh[128 * SSTR];
    __shared__ __align__(16) unsigned short sAl[128 * SSTR];
    __shared__ __align__(16) unsigned short sBh[128 * SSTR];
    __shared__ __align__(16) unsigned short sBl[128 * SSTR];

    const int tid = threadIdx.x;
    const int wid = tid >> 5;
    const int lane = tid & 31;
    const int wm = wid >> 2;          // 0..1 -> rows wm*64
    const int wn = wid & 3;           // 0..3 -> cols wn*32
    const int row0 = blockIdx.x * 128;
    const int col0 = blockIdx.y * 128;

    float acc[4][4][4];
    #pragma unroll
    for (int i = 0; i < 4; i++)
        #pragma unroll
        for (int j = 0; j < 4; j++)
            #pragma unroll
            for (int q = 0; q < 4; q++) acc[i][j][q] = 0.f;

    const uint32_t bAh = smem_u32(sAh);
    const uint32_t bAl = smem_u32(sAl);
    const uint32_t bBh = smem_u32(sBh);
    const uint32_t bBl = smem_u32(sBl);

    for (int k0 = 0; k0 < DH; k0 += 32) {
        // stage A (128 rows x 32 k) and B=W^T (128 out-cols x 32 k), hi+lo
        #pragma unroll
        for (int l = 0; l < 2; l++) {
            int idx = tid + l * 256;          // 0..511
            int r = idx >> 2, v = idx & 3;    // 4 x uint4 (8 bf16) per row
            int row = row0 + r;
            uint4 hv = make_uint4(0, 0, 0, 0), lv = make_uint4(0, 0, 0, 0);
            if (row < N) {
                size_t go = (size_t)row * DH + k0 + v * 8;
                hv = *(const uint4*)&g_ah[go];
                lv = *(const uint4*)&g_al[go];
            }
            *(uint4*)&sAh[r * SSTR + v * 8] = hv;
            *(uint4*)&sAl[r * SSTR + v * 8] = lv;
        }
        #pragma unroll
        for (int l = 0; l < 2; l++) {
            int idx = tid + l * 256;
            int r = idx >> 2, v = idx & 3;
            size_t go = (size_t)woff + (size_t)(col0 + r) * DH + k0 + v * 8;
            *(uint4*)&sBh[r * SSTR + v * 8] = *(const uint4*)&g_wth[go];
            *(uint4*)&sBl[r * SSTR + v * 8] = *(const uint4*)&g_wtl[go];
        }
        __syncthreads();

        #pragma unroll
        for (int kk = 0; kk < 32; kk += 16) {
            uint32_t ah[4][4], al[4][4];
            // A frags: 4 m-tiles of 16 rows
            #pragma unroll
            for (int tm = 0; tm < 4; tm++) {
                int r = wm * 64 + tm * 16 + (lane & 15);
                uint32_t off = (uint32_t)(r * SSTR + kk + (lane >> 4) * 8) * 2;
                ldsm_x4(ah[tm][0], ah[tm][1], ah[tm][2], ah[tm][3], bAh + off);
                ldsm_x4(al[tm][0], al[tm][1], al[tm][2], al[tm][3], bAl + off);
            }
            // per n-tile: B hi/lo frags, then 3-term MMAs
            #pragma unroll
            for (int tn = 0; tn < 4; tn++) {
                int r = wn * 32 + tn * 8 + (lane & 7);
                uint32_t off = (uint32_t)(r * SSTR + kk + ((lane >> 3) & 1) * 8) * 2;
                uint32_t bh[2], bl[2];
                ldsm_x2(bh[0], bh[1], bBh + off);
                ldsm_x2(bl[0], bl[1], bBl + off);
                #pragma unroll
                for (int tm = 0; tm < 4; tm++) {
                    mma16816(acc[tm][tn], ah[tm], bh);
                    mma16816(acc[tm][tn], al[tm], bh);
                    mma16816(acc[tm][tn], ah[tm], bl);
                }
            }
        }
        __syncthreads();
    }

    // epilogue: fragment layout -> fp32 g_h
    #pragma unroll
    for (int tm = 0; tm < 4; tm++) {
        int r0r = row0 + wm * 64 + tm * 16 + (lane >> 2);
        #pragma unroll
        for (int tn = 0; tn < 4; tn++) {
            int col = col0 + wn * 32 + tn * 8 + (lane & 3) * 2;
            if (r0r < N)
                *(float2*)&g_h[(size_t)r0r * M + col] =
                    make_float2(acc[tm][tn][0], acc[tm][tn][1]);
            if (r0r + 8 < N)
                *(float2*)&g_h[(size_t)(r0r + 8) * M + col] =
                    make_float2(acc[tm][tn][2], acc[tm][tn][3]);
        }
    }
}

// ---------------- aggregation (gather, atomic-free) --------------------------
__global__ void k_agg(const float* __restrict__ b, float* __restrict__ oext,
                      int M, int useExt)
{
    float* out = useExt ? oext : g_a;
    int node = blockIdx.x;
    int c    = threadIdx.x;

    float di = g_dinv[node];
    float s  = di * di;
    float4 hv = *(const float4*)&g_h[(size_t)node * M + c * 4];
    float4 bv = *(const float4*)&b[c * 4];
    float4 acc;
    acc.x = fmaf(hv.x, s, bv.x);
    acc.y = fmaf(hv.y, s, bv.y);
    acc.z = fmaf(hv.z, s, bv.z);
    acc.w = fmaf(hv.w, s, bv.w);

    int e   = g_rowptr[node];
    int end = g_rowptr[node + 1];
    for (; e + 1 < end; e += 2) {
        int   s0 = g_csr_src[e];
        int   s1 = g_csr_src[e + 1];
        float w0 = g_csr_w[e];
        float w1 = g_csr_w[e + 1];
        float4 v0 = *(const float4*)&g_h[(size_t)s0 * M + c * 4];
        float4 v1 = *(const float4*)&g_h[(size_t)s1 * M + c * 4];
        acc.x = fmaf(v0.x, w0, acc.x); acc.y = fmaf(v0.y, w0, acc.y);
        acc.z = fmaf(v0.z, w0, acc.z); acc.w = fmaf(v0.w, w0, acc.w);
        acc.x = fmaf(v1.x, w1, acc.x); acc.y = fmaf(v1.y, w1, acc.y);
        acc.z = fmaf(v1.z, w1, acc.z); acc.w = fmaf(v1.w, w1, acc.w);
    }
    if (e < end) {
        int   s0 = g_csr_src[e];
        float w0 = g_csr_w[e];
        float4 v0 = *(const float4*)&g_h[(size_t)s0 * M + c * 4];
        acc.x = fmaf(v0.x, w0, acc.x); acc.y = fmaf(v0.y, w0, acc.y);
        acc.z = fmaf(v0.z, w0, acc.z); acc.w = fmaf(v0.w, w0, acc.w);
    }
    *(float4*)&out[(size_t)node * M + c * 4] = acc;
}

// ---------------- launch -----------------------------------------------------
extern "C" void kernel_launch(void* const* d_in, const int* in_sizes, int n_in,
                              void* d_out, int out_size)
{
    const float* x  = (const float*)d_in[0];
    const void*  ei = d_in[1];
    const float* W1 = (const float*)d_in[2];
    const float* b1 = (const float*)d_in[3];
    const float* W2 = (const float*)d_in[4];
    const float* b2 = (const float*)d_in[5];
    const float* W3 = (const float*)d_in[6];
    const float* b3 = (const float*)d_in[7];
    float* out = (float*)d_out;

    const int N = NN;
    const int E = in_sizes[1] / 2;

    // ---- one-time prep
    k_detect  <<<1, 256>>>((const int*)ei);
    k_cnt_init<<<(N + 255) / 256, 256>>>(N);
    k_cnt_acc <<<(E + 255) / 256, 256>>>(ei, E);
    k_dinv    <<<(N + 255) / 256, 256>>>(N);
    k_prep    <<<(E + 255) / 256, 256>>>(ei, E);
    k_scan    <<<1, 1024>>>();
    k_fill    <<<(E + 255) / 256, 256>>>(E);

    k_wprep<<<(65536 + 255) / 256, 256>>>(W1, DH, DH, 0);
    k_wprep<<<(65536 + 255) / 256, 256>>>(W2, DH, DH, 65536);
    k_wprep<<<(32768 + 255) / 256, 256>>>(W3, DH, DOUT, 2 * 65536);

    const int n4 = N * (DH / 4);
    dim3 tg_h((N + 127) / 128, DH / 128);    // 391 x 2
    dim3 tg_o((N + 127) / 128, DOUT / 128);  // 391 x 1

    // ---- layer 1
    k_split <<<(n4 + 255) / 256, 256>>>(x, n4, 0, 1);
    k_mgemm <<<tg_h, 256>>>(N, DH, 0);
    k_agg   <<<N, DH / 4>>>(b1, out, DH, 0);

    // ---- layer 2
    k_split <<<(n4 + 255) / 256, 256>>>(x, n4, 1, 0);
    k_mgemm <<<tg_h, 256>>>(N, DH, 65536);
    k_agg   <<<N, DH / 4>>>(b2, out, DH, 0);

    // ---- layer 3
    k_split <<<(n4 + 255) / 256, 256>>>(x, n4, 1, 0);
    k_mgemm <<<tg_o, 256>>>(N, DOUT, 2 * 65536);
    k_agg   <<<N, DOUT / 4>>>(b3, out, DOUT, 1);
}

// round 7
// speedup vs baseline: 3.0160x; 1.0156x over previous
#include <cuda_runtime.h>
#include <cuda_bf16.h>
#include <math.h>
#include <stdint.h>

#define NN    50000
#define DH    256
#define DOUT  128
#define EMAX  800000

// ---------------- scratch (device globals; referenced by symbol only) --------
__device__ float g_h   [(size_t)NN * DH];        // GEMM output (fp32)
__device__ __nv_bfloat16 g_ah[(size_t)NN * DH];  // A split hi (GEMM input)
__device__ __nv_bfloat16 g_al[(size_t)NN * DH];  // A split lo
__device__ __nv_bfloat16 g_wth[2 * 65536 + 32768]; // W^T hi (3 layers, [m][k])
__device__ __nv_bfloat16 g_wtl[2 * 65536 + 32768]; // W^T lo
__device__ float g_dinv[NN];
__device__ int   g_cnt [NN];
__device__ int   g_rowptr[NN + 1];
__device__ int   g_cursor[NN];
__device__ int   g_src [EMAX];
__device__ int   g_dst [EMAX];
__device__ float g_norm[EMAX];
__device__ int   g_csr_src[EMAX];
__device__ float g_csr_w  [EMAX];
__device__ int   g_is64;

__device__ __forceinline__ uint32_t smem_u32(const void* p) {
    uint32_t a;
    asm("{ .reg .u64 t; cvta.to.shared.u64 t, %1; cvt.u32.u64 %0, t; }"
        : "=r"(a) : "l"(p));
    return a;
}

// ---------------- dtype probe ------------------------------------------------
__global__ void k_detect(const int* __restrict__ ei32) {
    __shared__ int any;
    if (threadIdx.x == 0) any = 0;
    __syncthreads();
    for (int k = threadIdx.x; k < 1024; k += blockDim.x)
        if (ei32[2 * k + 1] != 0) atomicOr(&any, 1);
    __syncthreads();
    if (threadIdx.x == 0) g_is64 = any ? 0 : 1;
}

__device__ __forceinline__ int ld_idx(const void* ei, size_t pos) {
    int v;
    if (g_is64) v = (int)((const long long*)ei)[pos];
    else        v = ((const int*)ei)[pos];
    return min(max(v, 0), NN - 1);
}

// ---------------- degree / CSR prep ------------------------------------------
__global__ void k_cnt_init(int n) {
    int i = blockIdx.x * blockDim.x + threadIdx.x;
    if (i < n) g_cnt[i] = 0;
}
__global__ void k_cnt_acc(const void* __restrict__ ei, int E) {
    int e = blockIdx.x * blockDim.x + threadIdx.x;
    if (e < E) atomicAdd(&g_cnt[ld_idx(ei, (size_t)E + e)], 1);
}
__global__ void k_dinv(int n) {
    int i = blockIdx.x * blockDim.x + threadIdx.x;
    if (i < n) g_dinv[i] = rsqrtf(1.0f + (float)g_cnt[i]);
}
__global__ void k_prep(const void* __restrict__ ei, int E) {
    int e = blockIdx.x * blockDim.x + threadIdx.x;
    if (e < E) {
        int s = ld_idx(ei, (size_t)e);
        int d = ld_idx(ei, (size_t)E + e);
        g_src[e]  = s;
        g_dst[e]  = d;
        g_norm[e] = g_dinv[s] * g_dinv[d];
    }
}
__global__ void k_scan() {
    const int T = 1024;
    __shared__ int part[T];
    int tid = threadIdx.x;
    int chunk = (NN + T - 1) / T;
    int base = tid * chunk;
    int sum = 0;
    for (int i = 0; i < chunk; i++) {
        int j = base + i;
        if (j < NN) sum += g_cnt[j];
    }
    part[tid] = sum;
    __syncthreads();
    for (int off = 1; off < T; off <<= 1) {
        int v = (tid >= off) ? part[tid - off] : 0;
        __syncthreads();
        part[tid] += v;
        __syncthreads();
    }
    int run = (tid > 0) ? part[tid - 1] : 0;
    for (int i = 0; i < chunk; i++) {
        int j = base + i;
        if (j < NN) {
            int c = g_cnt[j];
            g_rowptr[j] = run;
            g_cursor[j] = run;
            run += c;
        }
    }
    if (tid == T - 1) g_rowptr[NN] = run;
}
__global__ void k_fill(int E) {
    int e = blockIdx.x * blockDim.x + threadIdx.x;
    if (e < E) {
        int d   = g_dst[e];
        int pos = atomicAdd(&g_cursor[d], 1);
        g_csr_src[pos] = g_src[e];
        g_csr_w  [pos] = g_norm[e];
    }
}

// ---------------- hi/lo split ---------------------------------------------------
__device__ __forceinline__ void split1(float v, unsigned short& hb, unsigned short& lb) {
    __nv_bfloat16 h = __float2bfloat16(v);
    float hf = __bfloat162float(h);
    __nv_bfloat16 l = __float2bfloat16(v - hf);
    hb = reinterpret_cast<unsigned short&>(h);
    lb = reinterpret_cast<unsigned short&>(l);
}

// layer-1 input: x fp32 -> g_ah/g_al (no relu)
__global__ void k_split_x(const float* __restrict__ x, int n4) {
    int i = blockIdx.x * blockDim.x + threadIdx.x;
    if (i < n4) {
        float4 v = ((const float4*)x)[i];
        ushort4 hv, lv;
        split1(v.x, hv.x, lv.x);
        split1(v.y, hv.y, lv.y);
        split1(v.z, hv.z, lv.z);
        split1(v.w, hv.w, lv.w);
        ((ushort4*)g_ah)[i] = hv;
        ((ushort4*)g_al)[i] = lv;
    }
}

// weights: W[K,M] fp32 -> Wt[m][k] bf16 hi/lo at offset off
__global__ void k_wprep(const float* __restrict__ W, int K, int M, int off) {
    int i = blockIdx.x * blockDim.x + threadIdx.x;
    if (i < K * M) {
        int k = i / M, m = i % M;
        unsigned short hb, lb;
        split1(W[i], hb, lb);
        g_wth[off + (size_t)m * K + k] = reinterpret_cast<__nv_bfloat16&>(hb);
        g_wtl[off + (size_t)m * K + k] = reinterpret_cast<__nv_bfloat16&>(lb);
    }
}

// ---------------- mma.sync bf16 split GEMM ------------------------------------
#define SSTR 40

__device__ __forceinline__ void ldsm_x4(uint32_t& r0, uint32_t& r1,
                                        uint32_t& r2, uint32_t& r3, uint32_t a) {
    asm volatile("ldmatrix.sync.aligned.m8n8.x4.shared.b16 {%0,%1,%2,%3}, [%4];"
                 : "=r"(r0), "=r"(r1), "=r"(r2), "=r"(r3) : "r"(a));
}
__device__ __forceinline__ void ldsm_x2(uint32_t& r0, uint32_t& r1, uint32_t a) {
    asm volatile("ldmatrix.sync.aligned.m8n8.x2.shared.b16 {%0,%1}, [%2];"
                 : "=r"(r0), "=r"(r1) : "r"(a));
}
__device__ __forceinline__ void mma16816(float* d, const uint32_t* a, const uint32_t* b) {
    asm volatile(
        "mma.sync.aligned.m16n8k16.row.col.f32.bf16.bf16.f32 "
        "{%0,%1,%2,%3}, {%4,%5,%6,%7}, {%8,%9}, {%0,%1,%2,%3};"
        : "+f"(d[0]), "+f"(d[1]), "+f"(d[2]), "+f"(d[3])
        : "r"(a[0]), "r"(a[1]), "r"(a[2]), "r"(a[3]), "r"(b[0]), "r"(b[1]));
}

__global__ __launch_bounds__(256, 1) void k_mgemm(int N, int M, int woff) {
    __shared__ __align__(16) unsigned short sAh[128 * SSTR];
    __shared__ __align__(16) unsigned short sAl[128 * SSTR];
    __shared__ __align__(16) unsigned short sBh[128 * SSTR];
    __shared__ __align__(16) unsigned short sBl[128 * SSTR];

    const int tid = threadIdx.x;
    const int wid = tid >> 5;
    const int lane = tid & 31;
    const int wm = wid >> 2;
    const int wn = wid & 3;
    const int row0 = blockIdx.x * 128;
    const int col0 = blockIdx.y * 128;

    float acc[4][4][4];
    #pragma unroll
    for (int i = 0; i < 4; i++)
        #pragma unroll
        for (int j = 0; j < 4; j++)
            #pragma unroll
            for (int q = 0; q < 4; q++) acc[i][j][q] = 0.f;

    const uint32_t bAh = smem_u32(sAh);
    const uint32_t bAl = smem_u32(sAl);
    const uint32_t bBh = smem_u32(sBh);
    const uint32_t bBl = smem_u32(sBl);

    for (int k0 = 0; k0 < DH; k0 += 32) {
        #pragma unroll
        for (int l = 0; l < 2; l++) {
            int idx = tid + l * 256;
            int r = idx >> 2, v = idx & 3;
            int row = row0 + r;
            uint4 hv = make_uint4(0, 0, 0, 0), lv = make_uint4(0, 0, 0, 0);
            if (row < N) {
                size_t go = (size_t)row * DH + k0 + v * 8;
                hv = *(const uint4*)&g_ah[go];
                lv = *(const uint4*)&g_al[go];
            }
            *(uint4*)&sAh[r * SSTR + v * 8] = hv;
            *(uint4*)&sAl[r * SSTR + v * 8] = lv;
        }
        #pragma unroll
        for (int l = 0; l < 2; l++) {
            int idx = tid + l * 256;
            int r = idx >> 2, v = idx & 3;
            size_t go = (size_t)woff + (size_t)(col0 + r) * DH + k0 + v * 8;
            *(uint4*)&sBh[r * SSTR + v * 8] = *(const uint4*)&g_wth[go];
            *(uint4*)&sBl[r * SSTR + v * 8] = *(const uint4*)&g_wtl[go];
        }
        __syncthreads();

        #pragma unroll
        for (int kk = 0; kk < 32; kk += 16) {
            uint32_t ah[4][4], al[4][4];
            #pragma unroll
            for (int tm = 0; tm < 4; tm++) {
                int r = wm * 64 + tm * 16 + (lane & 15);
                uint32_t off = (uint32_t)(r * SSTR + kk + (lane >> 4) * 8) * 2;
                ldsm_x4(ah[tm][0], ah[tm][1], ah[tm][2], ah[tm][3], bAh + off);
                ldsm_x4(al[tm][0], al[tm][1], al[tm][2], al[tm][3], bAl + off);
            }
            #pragma unroll
            for (int tn = 0; tn < 4; tn++) {
                int r = wn * 32 + tn * 8 + (lane & 7);
                uint32_t off = (uint32_t)(r * SSTR + kk + ((lane >> 3) & 1) * 8) * 2;
                uint32_t bh[2], bl[2];
                ldsm_x2(bh[0], bh[1], bBh + off);
                ldsm_x2(bl[0], bl[1], bBl + off);
                #pragma unroll
                for (int tm = 0; tm < 4; tm++) {
                    mma16816(acc[tm][tn], ah[tm], bh);
                    mma16816(acc[tm][tn], al[tm], bh);
                    mma16816(acc[tm][tn], ah[tm], bl);
                }
            }
        }
        __syncthreads();
    }

    #pragma unroll
    for (int tm = 0; tm < 4; tm++) {
        int r0r = row0 + wm * 64 + tm * 16 + (lane >> 2);
        #pragma unroll
        for (int tn = 0; tn < 4; tn++) {
            int col = col0 + wn * 32 + tn * 8 + (lane & 3) * 2;
            if (r0r < N)
                *(float2*)&g_h[(size_t)r0r * M + col] =
                    make_float2(acc[tm][tn][0], acc[tm][tn][1]);
            if (r0r + 8 < N)
                *(float2*)&g_h[(size_t)(r0r + 8) * M + col] =
                    make_float2(acc[tm][tn][2], acc[tm][tn][3]);
        }
    }
}

// ---------------- aggregation (gather) + fused relu/split --------------------
// acc = b + dinv^2*h[node] + sum norm*h[src].
// mode 0: write relu(acc) split into g_ah/g_al (feeds next GEMM)
// mode 1: write acc fp32 to oext (final layer)
__global__ void k_agg(const float* __restrict__ b, float* __restrict__ oext,
                      int M, int mode)
{
    int node = blockIdx.x;
    int c    = threadIdx.x;

    float di = g_dinv[node];
    float s  = di * di;
    float4 hv = *(const float4*)&g_h[(size_t)node * M + c * 4];
    float4 bv = *(const float4*)&b[c * 4];
    float4 acc;
    acc.x = fmaf(hv.x, s, bv.x);
    acc.y = fmaf(hv.y, s, bv.y);
    acc.z = fmaf(hv.z, s, bv.z);
    acc.w = fmaf(hv.w, s, bv.w);

    int e   = g_rowptr[node];
    int end = g_rowptr[node + 1];

    // unroll 4: batch independent loads for MLP
    for (; e + 3 < end; e += 4) {
        int   s0 = g_csr_src[e],     s1 = g_csr_src[e + 1];
        int   s2 = g_csr_src[e + 2], s3 = g_csr_src[e + 3];
        float w0 = g_csr_w[e],     w1 = g_csr_w[e + 1];
        float w2 = g_csr_w[e + 2], w3 = g_csr_w[e + 3];
        float4 v0 = *(const float4*)&g_h[(size_t)s0 * M + c * 4];
        float4 v1 = *(const float4*)&g_h[(size_t)s1 * M + c * 4];
        float4 v2 = *(const float4*)&g_h[(size_t)s2 * M + c * 4];
        float4 v3 = *(const float4*)&g_h[(size_t)s3 * M + c * 4];
        acc.x = fmaf(v0.x, w0, acc.x); acc.y = fmaf(v0.y, w0, acc.y);
        acc.z = fmaf(v0.z, w0, acc.z); acc.w = fmaf(v0.w, w0, acc.w);
        acc.x = fmaf(v1.x, w1, acc.x); acc.y = fmaf(v1.y, w1, acc.y);
        acc.z = fmaf(v1.z, w1, acc.z); acc.w = fmaf(v1.w, w1, acc.w);
        acc.x = fmaf(v2.x, w2, acc.x); acc.y = fmaf(v2.y, w2, acc.y);
        acc.z = fmaf(v2.z, w2, acc.z); acc.w = fmaf(v2.w, w2, acc.w);
        acc.x = fmaf(v3.x, w3, acc.x); acc.y = fmaf(v3.y, w3, acc.y);
        acc.z = fmaf(v3.z, w3, acc.z); acc.w = fmaf(v3.w, w3, acc.w);
    }
    for (; e < end; e++) {
        int   s0 = g_csr_src[e];
        float w0 = g_csr_w[e];
        float4 v0 = *(const float4*)&g_h[(size_t)s0 * M + c * 4];
        acc.x = fmaf(v0.x, w0, acc.x); acc.y = fmaf(v0.y, w0, acc.y);
        acc.z = fmaf(v0.z, w0, acc.z); acc.w = fmaf(v0.w, w0, acc.w);
    }

    if (mode == 0) {
        acc.x = fmaxf(acc.x, 0.f); acc.y = fmaxf(acc.y, 0.f);
        acc.z = fmaxf(acc.z, 0.f); acc.w = fmaxf(acc.w, 0.f);
        ushort4 hvs, lvs;
        split1(acc.x, hvs.x, lvs.x);
        split1(acc.y, hvs.y, lvs.y);
        split1(acc.z, hvs.z, lvs.z);
        split1(acc.w, hvs.w, lvs.w);
        size_t o = ((size_t)node * M) / 4 + c;
        ((ushort4*)g_ah)[o] = hvs;
        ((ushort4*)g_al)[o] = lvs;
    } else {
        *(float4*)&oext[(size_t)node * M + c * 4] = acc;
    }
}

// ---------------- launch -----------------------------------------------------
extern "C" void kernel_launch(void* const* d_in, const int* in_sizes, int n_in,
                              void* d_out, int out_size)
{
    const float* x  = (const float*)d_in[0];
    const void*  ei = d_in[1];
    const float* W1 = (const float*)d_in[2];
    const float* b1 = (const float*)d_in[3];
    const float* W2 = (const float*)d_in[4];
    const float* b2 = (const float*)d_in[5];
    const float* W3 = (const float*)d_in[6];
    const float* b3 = (const float*)d_in[7];
    float* out = (float*)d_out;

    const int N = NN;
    const int E = in_sizes[1] / 2;

    // ---- one-time prep
    k_detect  <<<1, 256>>>((const int*)ei);
    k_cnt_init<<<(N + 255) / 256, 256>>>(N);
    k_cnt_acc <<<(E + 255) / 256, 256>>>(ei, E);
    k_dinv    <<<(N + 255) / 256, 256>>>(N);
    k_prep    <<<(E + 255) / 256, 256>>>(ei, E);
    k_scan    <<<1, 1024>>>();
    k_fill    <<<(E + 255) / 256, 256>>>(E);

    k_wprep<<<(65536 + 255) / 256, 256>>>(W1, DH, DH, 0);
    k_wprep<<<(65536 + 255) / 256, 256>>>(W2, DH, DH, 65536);
    k_wprep<<<(32768 + 255) / 256, 256>>>(W3, DH, DOUT, 2 * 65536);

    const int n4 = N * (DH / 4);
    dim3 tg_h((N + 127) / 128, DH / 128);    // 391 x 2
    dim3 tg_o((N + 127) / 128, DOUT / 128);  // 391 x 1

    // ---- layer 1
    k_split_x<<<(n4 + 255) / 256, 256>>>(x, n4);
    k_mgemm  <<<tg_h, 256>>>(N, DH, 0);
    k_agg    <<<N, DH / 4>>>(b1, out, DH, 0);

    // ---- layer 2 (agg already produced relu'd hi/lo)
    k_mgemm  <<<tg_h, 256>>>(N, DH, 65536);
    k_agg    <<<N, DH / 4>>>(b2, out, DH, 0);

    // ---- layer 3
    k_mgemm  <<<tg_o, 256>>>(N, DOUT, 2 * 65536);
    k_agg    <<<N, DOUT / 4>>>(b3, out, DOUT, 1);
}

// round 8
// speedup vs baseline: 3.5611x; 1.1807x over previous
#include <cuda_runtime.h>
#include <cuda_bf16.h>
#include <math.h>
#include <stdint.h>

#define NN    50000
#define DH    256
#define DOUT  128
#define EMAX  800000

// ---------------- scratch (device globals; referenced by symbol only) --------
__device__ float g_h   [(size_t)NN * DH];        // GEMM output (fp32)
__device__ __nv_bfloat16 g_ah[(size_t)NN * DH];  // A split hi (GEMM input)
__device__ __nv_bfloat16 g_al[(size_t)NN * DH];  // A split lo
__device__ __nv_bfloat16 g_wth[2 * 65536 + 32768]; // W^T hi (3 layers, [m][k])
__device__ __nv_bfloat16 g_wtl[2 * 65536 + 32768]; // W^T lo
__device__ float g_dinv[NN];
__device__ int   g_cnt [NN];
__device__ int   g_rowptr[NN + 1];
__device__ int   g_cursor[NN];
__device__ int   g_src [EMAX];
__device__ int   g_dst [EMAX];
__device__ float g_norm[EMAX];
__device__ int   g_csr_src[EMAX];
__device__ float g_csr_w  [EMAX];
__device__ int   g_is64;

__device__ __forceinline__ uint32_t smem_u32(const void* p) {
    uint32_t a;
    asm("{ .reg .u64 t; cvta.to.shared.u64 t, %1; cvt.u32.u64 %0, t; }"
        : "=r"(a) : "l"(p));
    return a;
}

// ---------------- hi/lo split --------------------------------------------------
__device__ __forceinline__ void split1(float v, unsigned short& hb, unsigned short& lb) {
    __nv_bfloat16 h = __float2bfloat16(v);
    float hf = __bfloat162float(h);
    __nv_bfloat16 l = __float2bfloat16(v - hf);
    hb = reinterpret_cast<unsigned short&>(h);
    lb = reinterpret_cast<unsigned short&>(l);
}

// ---------------- prep kernels -------------------------------------------------
// all three weight matrices -> W^T hi/lo in one launch
__global__ void k_wprep_all(const float* __restrict__ W1,
                            const float* __restrict__ W2,
                            const float* __restrict__ W3) {
    int i = blockIdx.x * blockDim.x + threadIdx.x;
    const float* W; int M, off;
    if (i < 65536)            { W = W1; M = DH;   off = 0;       }
    else if (i < 131072)      { W = W2; M = DH;   off = 65536;   i -= 65536;  }
    else if (i < 163840)      { W = W3; M = DOUT; off = 131072;  i -= 131072; }
    else return;
    int k = i / M, m = i % M;
    unsigned short hb, lb;
    split1(W[i], hb, lb);
    g_wth[off + (size_t)m * DH + k] = reinterpret_cast<__nv_bfloat16&>(hb);
    g_wtl[off + (size_t)m * DH + k] = reinterpret_cast<__nv_bfloat16&>(lb);
}

__global__ void k_split_x(const float* __restrict__ x, int n4) {
    int i = blockIdx.x * blockDim.x + threadIdx.x;
    if (i < n4) {
        float4 v = ((const float4*)x)[i];
        ushort4 hv, lv;
        split1(v.x, hv.x, lv.x);
        split1(v.y, hv.y, lv.y);
        split1(v.z, hv.z, lv.z);
        split1(v.w, hv.w, lv.w);
        ((ushort4*)g_ah)[i] = hv;
        ((ushort4*)g_al)[i] = lv;
    }
}

// dtype probe (block 0) + zero g_cnt
__global__ void k_pre1(const int* __restrict__ ei32, int n) {
    int i = blockIdx.x * blockDim.x + threadIdx.x;
    if (i < n) g_cnt[i] = 0;
    if (blockIdx.x == 0) {
        __shared__ int any;
        if (threadIdx.x == 0) any = 0;
        __syncthreads();
        int a = 0;
        for (int k = threadIdx.x; k < 1024; k += blockDim.x)
            if (ei32[2 * k + 1] != 0) a = 1;
        if (a) atomicOr(&any, 1);
        __syncthreads();
        if (threadIdx.x == 0) g_is64 = any ? 0 : 1;
    }
}

__device__ __forceinline__ int ld_idx(const void* ei, size_t pos) {
    int v;
    if (g_is64) v = (int)((const long long*)ei)[pos];
    else        v = ((const int*)ei)[pos];
    return min(max(v, 0), NN - 1);
}

__global__ void k_cnt_acc(const void* __restrict__ ei, int E) {
    int e = blockIdx.x * blockDim.x + threadIdx.x;
    if (e < E) atomicAdd(&g_cnt[ld_idx(ei, (size_t)E + e)], 1);
}
__global__ void k_dinv(int n) {
    int i = blockIdx.x * blockDim.x + threadIdx.x;
    if (i < n) g_dinv[i] = rsqrtf(1.0f + (float)g_cnt[i]);
}
__global__ void k_prep(const void* __restrict__ ei, int E) {
    int e = blockIdx.x * blockDim.x + threadIdx.x;
    if (e < E) {
        int s = ld_idx(ei, (size_t)e);
        int d = ld_idx(ei, (size_t)E + e);
        g_src[e]  = s;
        g_dst[e]  = d;
        g_norm[e] = g_dinv[s] * g_dinv[d];
    }
}
__global__ void k_scan() {
    const int T = 1024;
    __shared__ int part[T];
    int tid = threadIdx.x;
    int chunk = (NN + T - 1) / T;
    int base = tid * chunk;
    int sum = 0;
    for (int i = 0; i < chunk; i++) {
        int j = base + i;
        if (j < NN) sum += g_cnt[j];
    }
    part[tid] = sum;
    __syncthreads();
    for (int off = 1; off < T; off <<= 1) {
        int v = (tid >= off) ? part[tid - off] : 0;
        __syncthreads();
        part[tid] += v;
        __syncthreads();
    }
    int run = (tid > 0) ? part[tid - 1] : 0;
    for (int i = 0; i < chunk; i++) {
        int j = base + i;
        if (j < NN) {
            int c = g_cnt[j];
            g_rowptr[j] = run;
            g_cursor[j] = run;
            run += c;
        }
    }
    if (tid == T - 1) g_rowptr[NN] = run;
}
__global__ void k_fill(int E) {
    int e = blockIdx.x * blockDim.x + threadIdx.x;
    if (e < E) {
        int d   = g_dst[e];
        int pos = atomicAdd(&g_cursor[d], 1);
        g_csr_src[pos] = g_src[e];
        g_csr_w  [pos] = g_norm[e];
    }
}

// ---------------- mma.sync bf16 split GEMM with cp.async double buffer ---------
#define SSTR 40
#define BUFSH 20480                 // shorts per buffer (4 arrays x 5120)

__device__ __forceinline__ void ldsm_x4(uint32_t& r0, uint32_t& r1,
                                        uint32_t& r2, uint32_t& r3, uint32_t a) {
    asm volatile("ldmatrix.sync.aligned.m8n8.x4.shared.b16 {%0,%1,%2,%3}, [%4];"
                 : "=r"(r0), "=r"(r1), "=r"(r2), "=r"(r3) : "r"(a));
}
__device__ __forceinline__ void ldsm_x2(uint32_t& r0, uint32_t& r1, uint32_t a) {
    asm volatile("ldmatrix.sync.aligned.m8n8.x2.shared.b16 {%0,%1}, [%2];"
                 : "=r"(r0), "=r"(r1) : "r"(a));
}
__device__ __forceinline__ void mma16816(float* d, const uint32_t* a, const uint32_t* b) {
    asm volatile(
        "mma.sync.aligned.m16n8k16.row.col.f32.bf16.bf16.f32 "
        "{%0,%1,%2,%3}, {%4,%5,%6,%7}, {%8,%9}, {%0,%1,%2,%3};"
        : "+f"(d[0]), "+f"(d[1]), "+f"(d[2]), "+f"(d[3])
        : "r"(a[0]), "r"(a[1]), "r"(a[2]), "r"(a[3]), "r"(b[0]), "r"(b[1]));
}
__device__ __forceinline__ void cp16(uint32_t d, const void* s, int sz) {
    asm volatile("cp.async.cg.shared.global [%0], [%1], 16, %2;"
                 :: "r"(d), "l"(s), "r"(sz));
}

__global__ __launch_bounds__(256) void k_mgemm(int N, int M, int woff) {
    extern __shared__ __align__(16) unsigned short smem[];

    const int tid = threadIdx.x;
    const int wid = tid >> 5;
    const int lane = tid & 31;
    const int wm = wid >> 2;
    const int wn = wid & 3;
    const int row0 = blockIdx.x * 128;
    const int col0 = blockIdx.y * 128;

    float acc[4][4][4];
    #pragma unroll
    for (int i = 0; i < 4; i++)
        #pragma unroll
        for (int j = 0; j < 4; j++)
            #pragma unroll
            for (int q = 0; q < 4; q++) acc[i][j][q] = 0.f;

    const uint32_t sbase = smem_u32(smem);

    // stage one K-chunk into buffer `buf` via cp.async (8 x 16B per thread)
    auto stage = [&](int buf, int k0) {
        uint32_t b0 = sbase + (uint32_t)buf * (BUFSH * 2);
        #pragma unroll
        for (int l = 0; l < 2; l++) {
            int idx = tid + l * 256;
            int r = idx >> 2, v = idx & 3;
            uint32_t d = b0 + (uint32_t)(r * SSTR + v * 8) * 2;
            int row = row0 + r;
            int sz = (row < N) ? 16 : 0;
            size_t ga = (size_t)row * DH + k0 + v * 8;
            cp16(d,             &g_ah[ga], sz);
            cp16(d + 5120 * 2,  &g_al[ga], sz);
            size_t gb = (size_t)woff + (size_t)(col0 + r) * DH + k0 + v * 8;
            cp16(d + 10240 * 2, &g_wth[gb], 16);
            cp16(d + 15360 * 2, &g_wtl[gb], 16);
        }
        asm volatile("cp.async.commit_group;");
    };

    stage(0, 0);

    for (int c = 0; c < 8; c++) {
        int buf = c & 1;
        if (c < 7) {
            stage(buf ^ 1, (c + 1) * 32);
            asm volatile("cp.async.wait_group 1;");
        } else {
            asm volatile("cp.async.wait_group 0;");
        }
        __syncthreads();

        uint32_t bAh = sbase + (uint32_t)buf * (BUFSH * 2);
        uint32_t bAl = bAh + 5120 * 2;
        uint32_t bBh = bAh + 10240 * 2;
        uint32_t bBl = bAh + 15360 * 2;

        #pragma unroll
        for (int kk = 0; kk < 32; kk += 16) {
            uint32_t ah[4][4], al[4][4];
            #pragma unroll
            for (int tm = 0; tm < 4; tm++) {
                int r = wm * 64 + tm * 16 + (lane & 15);
                uint32_t off = (uint32_t)(r * SSTR + kk + (lane >> 4) * 8) * 2;
                ldsm_x4(ah[tm][0], ah[tm][1], ah[tm][2], ah[tm][3], bAh + off);
                ldsm_x4(al[tm][0], al[tm][1], al[tm][2], al[tm][3], bAl + off);
            }
            #pragma unroll
            for (int tn = 0; tn < 4; tn++) {
                int r = wn * 32 + tn * 8 + (lane & 7);
                uint32_t off = (uint32_t)(r * SSTR + kk + ((lane >> 3) & 1) * 8) * 2;
                uint32_t bh[2], bl[2];
                ldsm_x2(bh[0], bh[1], bBh + off);
                ldsm_x2(bl[0], bl[1], bBl + off);
                #pragma unroll
                for (int tm = 0; tm < 4; tm++) {
                    mma16816(acc[tm][tn], ah[tm], bh);
                    mma16816(acc[tm][tn], al[tm], bh);
                    mma16816(acc[tm][tn], ah[tm], bl);
                }
            }
        }
        __syncthreads();
    }

    #pragma unroll
    for (int tm = 0; tm < 4; tm++) {
        int r0r = row0 + wm * 64 + tm * 16 + (lane >> 2);
        #pragma unroll
        for (int tn = 0; tn < 4; tn++) {
            int col = col0 + wn * 32 + tn * 8 + (lane & 3) * 2;
            if (r0r < N)
                *(float2*)&g_h[(size_t)r0r * M + col] =
                    make_float2(acc[tm][tn][0], acc[tm][tn][1]);
            if (r0r + 8 < N)
                *(float2*)&g_h[(size_t)(r0r + 8) * M + col] =
                    make_float2(acc[tm][tn][2], acc[tm][tn][3]);
        }
    }
}

// ---------------- aggregation (gather) + fused relu/split --------------------
__global__ void k_agg(const float* __restrict__ b, float* __restrict__ oext,
                      int M, int mode)
{
    int node = blockIdx.x;
    int c    = threadIdx.x;

    float di = g_dinv[node];
    float s  = di * di;
    float4 hv = *(const float4*)&g_h[(size_t)node * M + c * 4];
    float4 bv = *(const float4*)&b[c * 4];
    float4 acc;
    acc.x = fmaf(hv.x, s, bv.x);
    acc.y = fmaf(hv.y, s, bv.y);
    acc.z = fmaf(hv.z, s, bv.z);
    acc.w = fmaf(hv.w, s, bv.w);

    int e   = g_rowptr[node];
    int end = g_rowptr[node + 1];

    for (; e + 3 < end; e += 4) {
        int   s0 = g_csr_src[e],     s1 = g_csr_src[e + 1];
        int   s2 = g_csr_src[e + 2], s3 = g_csr_src[e + 3];
        float w0 = g_csr_w[e],     w1 = g_csr_w[e + 1];
        float w2 = g_csr_w[e + 2], w3 = g_csr_w[e + 3];
        float4 v0 = *(const float4*)&g_h[(size_t)s0 * M + c * 4];
        float4 v1 = *(const float4*)&g_h[(size_t)s1 * M + c * 4];
        float4 v2 = *(const float4*)&g_h[(size_t)s2 * M + c * 4];
        float4 v3 = *(const float4*)&g_h[(size_t)s3 * M + c * 4];
        acc.x = fmaf(v0.x, w0, acc.x); acc.y = fmaf(v0.y, w0, acc.y);
        acc.z = fmaf(v0.z, w0, acc.z); acc.w = fmaf(v0.w, w0, acc.w);
        acc.x = fmaf(v1.x, w1, acc.x); acc.y = fmaf(v1.y, w1, acc.y);
        acc.z = fmaf(v1.z, w1, acc.z); acc.w = fmaf(v1.w, w1, acc.w);
        acc.x = fmaf(v2.x, w2, acc.x); acc.y = fmaf(v2.y, w2, acc.y);
        acc.z = fmaf(v2.z, w2, acc.z); acc.w = fmaf(v2.w, w2, acc.w);
        acc.x = fmaf(v3.x, w3, acc.x); acc.y = fmaf(v3.y, w3, acc.y);
        acc.z = fmaf(v3.z, w3, acc.z); acc.w = fmaf(v3.w, w3, acc.w);
    }
    for (; e < end; e++) {
        int   s0 = g_csr_src[e];
        float w0 = g_csr_w[e];
        float4 v0 = *(const float4*)&g_h[(size_t)s0 * M + c * 4];
        acc.x = fmaf(v0.x, w0, acc.x); acc.y = fmaf(v0.y, w0, acc.y);
        acc.z = fmaf(v0.z, w0, acc.z); acc.w = fmaf(v0.w, w0, acc.w);
    }

    if (mode == 0) {
        acc.x = fmaxf(acc.x, 0.f); acc.y = fmaxf(acc.y, 0.f);
        acc.z = fmaxf(acc.z, 0.f); acc.w = fmaxf(acc.w, 0.f);
        ushort4 hvs, lvs;
        split1(acc.x, hvs.x, lvs.x);
        split1(acc.y, hvs.y, lvs.y);
        split1(acc.z, hvs.z, lvs.z);
        split1(acc.w, hvs.w, lvs.w);
        size_t o = ((size_t)node * M) / 4 + c;
        ((ushort4*)g_ah)[o] = hvs;
        ((ushort4*)g_al)[o] = lvs;
    } else {
        *(float4*)&oext[(size_t)node * M + c * 4] = acc;
    }
}

// ---------------- launch -----------------------------------------------------
extern "C" void kernel_launch(void* const* d_in, const int* in_sizes, int n_in,
                              void* d_out, int out_size)
{
    const float* x  = (const float*)d_in[0];
    const void*  ei = d_in[1];
    const float* W1 = (const float*)d_in[2];
    const float* b1 = (const float*)d_in[3];
    const float* W2 = (const float*)d_in[4];
    const float* b2 = (const float*)d_in[5];
    const float* W3 = (const float*)d_in[6];
    const float* b3 = (const float*)d_in[7];
    float* out = (float*)d_out;

    const int N = NN;
    const int E = in_sizes[1] / 2;
    const int n4 = N * (DH / 4);
    const int SM_BYTES = 2 * BUFSH * 2;   // 81920

    static int attr_done = 0;
    if (!attr_done) {
        cudaFuncSetAttribute(k_mgemm, cudaFuncAttributeMaxDynamicSharedMemorySize,
                             SM_BYTES);
        attr_done = 1;
    }

    dim3 tg_h((N + 127) / 128, DH / 128);    // 391 x 2
    dim3 tg_o((N + 127) / 128, DOUT / 128);  // 391 x 1

    // edge-independent prep first, so launch #5 is k_mgemm (ncu -s 5 target)
    k_wprep_all<<<(163840 + 255) / 256, 256>>>(W1, W2, W3);        // 0
    k_split_x  <<<(n4 + 255) / 256, 256>>>(x, n4);                 // 1
    k_pre1     <<<(N + 255) / 256, 256>>>((const int*)ei, N);      // 2
    k_cnt_acc  <<<(E + 255) / 256, 256>>>(ei, E);                  // 3
    k_dinv     <<<(N + 255) / 256, 256>>>(N);                      // 4
    k_mgemm    <<<tg_h, 256, SM_BYTES>>>(N, DH, 0);                // 5 <- profiled
    k_prep     <<<(E + 255) / 256, 256>>>(ei, E);                  // 6
    k_scan     <<<1, 1024>>>();                                    // 7
    k_fill     <<<(E + 255) / 256, 256>>>(E);                      // 8
    k_agg      <<<N, DH / 4>>>(b1, out, DH, 0);                    // 9

    k_mgemm    <<<tg_h, 256, SM_BYTES>>>(N, DH, 65536);            // 10
    k_agg      <<<N, DH / 4>>>(b2, out, DH, 0);                    // 11

    k_mgemm    <<<tg_o, 256, SM_BYTES>>>(N, DOUT, 131072);         // 12
    k_agg      <<<N, DOUT / 4>>>(b3, out, DOUT, 1);                // 13
}